// round 3
// baseline (speedup 1.0000x reference)
#include <cuda_runtime.h>

// ----------------------------------------------------------------------------
// Preprocess_51024211476486: per-segment mean/std of gathered landmarks.
//   frames: [T=32768, 543, 3] f32  ->  out: [64, 328] f32
// Fused single kernel: 2048 CTAs (64 segments x 32 slices of 16 frames),
// last-arriving CTA per segment reduces the 32 partials and writes output.
// Segment boundaries b[s] = (s*32767)>>6 reproduce fp32 linspace exactly.
// ----------------------------------------------------------------------------

#define T_FRAMES     32768
#define FRAME_STRIDE 1629        // 543*3 floats per frame
#define L_SEG        64
#define NK           164         // 82 landmarks * 2 coords
#define SLICES       32
#define CHUNK        16
#define NBLK         (L_SEG * SLICES)   // 2048

__device__ __constant__ int LIPS_IDX_D[40] = {
    61, 185, 40, 39, 37, 0, 267, 269, 270, 409, 291, 146, 91, 181, 84, 17,
    314, 405, 321, 375, 78, 191, 80, 81, 82, 13, 312, 311, 310, 415, 95, 88,
    178, 87, 14, 317, 402, 318, 324, 308
};

// Per-slice partials: [field (sum/sq/cnt)][block][k]. Every element rewritten
// each launch (no zeroing needed); ~4 MB -> mostly L2-resident between the
// producer CTAs and the per-segment finalizer.
__device__ float g_partial[3][NBLK][NK];
// Per-segment arrival tickets. Zero at module load; the finalizing CTA resets
// its counter to 0, so every graph replay starts from a clean state.
__device__ int g_count[L_SEG];

__device__ __forceinline__ int lm_of_j(int j) {
    if (j < 21) return 468 + j;          // left hand
    if (j < 42) return 501 + j;          // right hand: 522 + (j-21)
    return LIPS_IDX_D[j - 42];           // lips gather
}

extern "C" __global__ void __launch_bounds__(192)
fused_stats_kernel(const float* __restrict__ frames, float* __restrict__ out)
{
    __shared__ int s_last;
    const int k     = threadIdx.x;
    const int blk   = blockIdx.x;               // 0..2047
    const int seg   = blk >> 5;
    const int slice = blk & 31;

    if (k < NK) {
        const int s0 = (seg * (T_FRAMES - 1)) >> 6;
        const int s1 = ((seg + 1) * (T_FRAMES - 1)) >> 6;
        const int f0 = s0 + slice * CHUNK;
        const int n  = min(s1 - f0, CHUNK);     // 15 or 16

        const int j = k >> 1;
        const int c = k & 1;
        const int off = lm_of_j(j) * 3 + c;
        const float* __restrict__ p =
            frames + (size_t)f0 * FRAME_STRIDE + off;

        // Unconditional 16 loads, compile-time immediate offsets (MLP=16).
        // Worst-case address: f0+15 = 32766 < 32768, always in-bounds; the
        // i >= n case is masked out of the accumulation below.
        float v[CHUNK];
        #pragma unroll
        for (int i = 0; i < CHUNK; i++)
            v[i] = __ldg(p + i * FRAME_STRIDE);

        float sum = 0.f, sq = 0.f, cnt = 0.f;
        #pragma unroll
        for (int i = 0; i < CHUNK; i++) {
            bool ok = (v[i] == v[i]) && (i < n);  // !isnan and inside slice
            float vv = ok ? v[i] : 0.f;
            sum += vv;
            sq   = fmaf(vv, vv, sq);
            cnt += ok ? 1.f : 0.f;
        }

        g_partial[0][blk][k] = sum;
        g_partial[1][blk][k] = sq;
        g_partial[2][blk][k] = cnt;
    }

    // Release partials, then take a ticket for this segment (CUB-style
    // last-block pattern; wait-free, no spinning).
    __syncthreads();
    __threadfence();
    if (threadIdx.x == 0) {
        int old = atomicAdd(&g_count[seg], 1);
        s_last = (old == SLICES - 1) ? 1 : 0;
    }
    __syncthreads();
    if (!s_last) return;

    __threadfence();   // acquire: order partial reads after the ticket

    if (k < NK) {
        float sum = 0.f, sq = 0.f, cnt = 0.f;
        const int base = seg * SLICES;
        #pragma unroll
        for (int s = 0; s < SLICES; s++) {
            sum += g_partial[0][base + s][k];
            sq  += g_partial[1][base + s][k];
            cnt += g_partial[2][base + s][k];
        }

        float mean = sum / cnt;
        float var  = sq / cnt - mean * mean;     // == two-pass s2/cnt
        var = fmaxf(var, 0.f);
        float stdv = sqrtf(var);

        if (!(mean == mean)) mean = 0.f;         // reference: isnan -> 0
        if (!(stdv == stdv)) stdv = 0.f;

        // stats layout [seg, 328]: mean at k, std at 164+k.
        out[seg * 328 + k]       = mean;
        out[seg * 328 + 164 + k] = stdv;
    }
    if (threadIdx.x == 0) g_count[seg] = 0;      // clean state for next replay
}

extern "C" void kernel_launch(void* const* d_in, const int* in_sizes, int n_in,
                              void* d_out, int out_size)
{
    const float* frames = (const float*)d_in[0];
    float* out = (float*)d_out;
    fused_stats_kernel<<<NBLK, 192>>>(frames, out);
}